// round 15
// baseline (speedup 1.0000x reference)
#include <cuda_runtime.h>
#include <cuda_fp16.h>

// LBP uniform (P=8, R=1) over (B,C,H,W)=(32,3,512,512) float32.
// R15 = R14 (2 out rows/warp, pipelined coalesced chunks, f16x2 compares,
// f32x2 packed scaling, STG.128) + latency/XU attack:
//  - depth-3 hfma2 tree (was serial depth 7)
//  - code accumulated as (1024+code): half bits = 0x6400|code -> both pixel
//    codes extracted with LOP3/BFE, NO F2I
//  - float(lbp)/255 via int_as_float(0x4B000000|lbp) + one exact FFMA,
//    NO I2F, NO FMUL

#define IMG_W 512
#define IMG_H 512
#define FULL 0xFFFFFFFFu

__device__ __forceinline__ unsigned prmt(unsigned a, unsigned b, unsigned sel) {
    unsigned d;
    asm("prmt.b32 %0, %1, %2, %3;" : "=r"(d) : "r"(a), "r"(b), "r"(sel));
    return d;
}

// two packed floats (lo,hi) * 255 -> f16x2 (RZ). Exact: RN f32 mul then RZ.
__device__ __forceinline__ unsigned conv2(unsigned long long px2) {
    unsigned d;
    asm("{\n\t"
        ".reg .b64 t;\n\t"
        ".reg .f32 lo, hi;\n\t"
        "mul.rn.f32x2 t, %1, %2;\n\t"
        "mov.b64 {lo, hi}, t;\n\t"
        "cvt.rz.f16x2.f32 %0, hi, lo;\n\t"
        "}"
        : "=r"(d) : "l"(px2), "l"(0x437F0000437F0000ull));  // 255.0f x2
    return d;
}

__device__ __forceinline__ __half2 u2h(unsigned x) {
    __half2 h;
    *reinterpret_cast<unsigned*>(&h) = x;
    return h;
}

// depth-3 weighted tree; returns bits of half2(1024 + code) per pixel
__device__ __forceinline__ unsigned code1024(unsigned tl, unsigned t, unsigned tr,
                                             unsigned r, unsigned br, unsigned b,
                                             unsigned bl, unsigned l, __half2 fc) {
    const __half2 TWO  = u2h(0x40004000u);
    const __half2 FOUR = u2h(0x44004400u);
    const __half2 SIXT = u2h(0x4C004C00u);
    const __half2 K1K  = u2h(0x64006400u);   // 1024.0 x2
    // circular order bits 0..7: tl, t, tr, r, br, b, bl, l
    const __half2 g0 = __hge2(u2h(tl), fc);
    const __half2 g1 = __hge2(u2h(t),  fc);
    const __half2 g2 = __hge2(u2h(tr), fc);
    const __half2 g3 = __hge2(u2h(r),  fc);
    const __half2 g4 = __hge2(u2h(br), fc);
    const __half2 g5 = __hge2(u2h(b),  fc);
    const __half2 g6 = __hge2(u2h(bl), fc);
    const __half2 g7 = __hge2(u2h(l),  fc);
    const __half2 u01 = __hfma2(g1, TWO, g0);    // g0 + 2 g1
    const __half2 u23 = __hfma2(g3, TWO, g2);    // (g2 + 2 g3) * 4
    const __half2 u45 = __hfma2(g5, TWO, g4);    // (g4 + 2 g5) * 16
    const __half2 u67 = __hfma2(g7, TWO, g6);    // (g6 + 2 g7) * 64
    const __half2 v0  = __hfma2(u23, FOUR, u01);
    const __half2 v1  = __hfma2(u67, FOUR, u45);
    __half2 m = __hfma2(v1, SIXT, v0);
    m = __hadd2(m, K1K);                         // exact: 1024+code < 2048
    return *reinterpret_cast<unsigned*>(&m);
}

// uniform-LBP tail from 8-bit code (no cvt instructions)
__device__ __forceinline__ float lbp_res(unsigned m) {
    const unsigned mm  = m * 0x101u;          // m | m<<8
    const unsigned rot = (mm >> 7) & 0xFFu;   // circular rot-left-1
    const int trans = __popc(m ^ rot);
    const int ones  = __popc(m);
    const int lbp   = (trans <= 2) ? ones : 9;
    const float f = __int_as_float(0x4B000000 | lbp);   // 2^23 + lbp exactly
    // fma(f, 1/255, -2^23*(1/255)): exact cancellation -> RN(lbp * (1/255f))
    return fmaf(f, 1.0f / 255.0f, -32896.50390625f);
}

// load one chunk (4 px) of one row, convert to two f16x2 words
__device__ __forceinline__ void load4(const float* p, unsigned& w0, unsigned& w1) {
    const ulonglong2 u = *reinterpret_cast<const ulonglong2*>(p);
    w0 = conv2(u.x);
    w1 = conv2(u.y);
}

__global__ __launch_bounds__(256, 6)
void lbp_kernel(const float* __restrict__ x, float* __restrict__ out, int npairs) {
    const int pr   = blockIdx.x * (blockDim.x >> 5) + (threadIdx.x >> 5);
    const int lane = threadIdx.x & 31;
    if (pr >= npairs) return;

    const int r0 = pr * 2;                 // even; pair stays inside one image
    const int h0 = r0 & (IMG_H - 1);
    const bool hasTop = (h0 != 0);
    const bool hasBot = (h0 != IMG_H - 2);

    const float* rb = x + (size_t)r0 * IMG_W + lane * 4;   // row r0
    const float* ra = rb - IMG_W;                           // row r0-1
    const float* rc = rb + IMG_W;                           // row r0+1
    const float* rd = rb + 2 * IMG_W;                       // row r0+2
    float* op0 = out + (size_t)r0 * IMG_W + lane * 4;
    float* op1 = op0 + IMG_W;

    const int upLane = (lane + 31) & 31;
    const int dnLane = (lane + 1) & 31;

    // prev-chunk edge words (word[1]) per row; 0 at left image border
    unsigned pa1 = 0u, pb1 = 0u, pc1 = 0u, pd1 = 0u;
    // current chunk: rows a (top), b (=r0), c (=r1), d (bottom)
    unsigned a0, a1, b0, b1, c0, c1, d0, d1;
    if (hasTop) load4(ra, a0, a1); else { a0 = 0u; a1 = 0u; }
    load4(rb, b0, b1);
    load4(rc, c0, c1);
    if (hasBot) load4(rd, d0, d1); else { d0 = 0u; d1 = 0u; }

#pragma unroll
    for (int k = 0; k < 4; k++) {
        // lookahead: next chunk
        unsigned na0 = 0u, na1 = 0u, nb0 = 0u, nb1 = 0u;
        unsigned nc0 = 0u, nc1 = 0u, nd0 = 0u, nd1 = 0u;
        if (k < 3) {
            const int off = 128 * (k + 1);
            if (hasTop) load4(ra + off, na0, na1);
            load4(rb + off, nb0, nb1);
            load4(rc + off, nc0, nc1);
            if (hasBot) load4(rd + off, nd0, nd1);
        }

        // halos: left = word1 of lane-1 (lane0 <- lane31's prev chunk);
        //        right = word0 of lane+1 (lane31 <- lane0's next chunk)
        unsigned ls, rs;
        ls = (lane == 31) ? pa1 : a1;  const unsigned aal = __shfl_sync(FULL, ls, upLane);
        rs = (lane == 0)  ? na0 : a0;  const unsigned aar = __shfl_sync(FULL, rs, dnLane);
        ls = (lane == 31) ? pb1 : b1;  const unsigned bal = __shfl_sync(FULL, ls, upLane);
        rs = (lane == 0)  ? nb0 : b0;  const unsigned bar = __shfl_sync(FULL, rs, dnLane);
        ls = (lane == 31) ? pc1 : c1;  const unsigned cal = __shfl_sync(FULL, ls, upLane);
        rs = (lane == 0)  ? nc0 : c0;  const unsigned car = __shfl_sync(FULL, rs, dnLane);
        ls = (lane == 31) ? pd1 : d1;  const unsigned dal = __shfl_sync(FULL, ls, upLane);
        rs = (lane == 0)  ? nd0 : d0;  const unsigned dar = __shfl_sync(FULL, rs, dnLane);

        // shifted windows per row: m=(px-1,px0) mid=(px1,px2) p=(px3,px4)
        const unsigned am = prmt(aal, a0, 0x5432u), amid = prmt(a0, a1, 0x5432u), ap = prmt(a1, aar, 0x5432u);
        const unsigned bm = prmt(bal, b0, 0x5432u), bmid = prmt(b0, b1, 0x5432u), bp = prmt(b1, bar, 0x5432u);
        const unsigned cm = prmt(cal, c0, 0x5432u), cmid = prmt(c0, c1, 0x5432u), cp = prmt(c1, car, 0x5432u);
        const unsigned dm = prmt(dal, d0, 0x5432u), dmid = prmt(d0, d1, 0x5432u), dp = prmt(d1, dar, 0x5432u);

        float res0[4], res1[4];
#pragma unroll
        for (int p = 0; p < 2; p++) {
            // output row 0: top=a, center=b, bottom=c
            const __half2 fc0 = h2floor(u2h(p ? b1 : b0));
            // output row 1: top=b, center=c, bottom=d
            const __half2 fc1 = h2floor(u2h(p ? c1 : c0));

            const unsigned u0 = code1024(
                p ? amid : am, p ? a1 : a0, p ? ap : amid,   // tl, t, tr
                p ? bp : bmid,                               // r
                p ? cp : cmid, p ? c1 : c0, p ? cmid : cm,   // br, b, bl
                p ? bmid : bm,                               // l
                fc0);
            const unsigned u1 = code1024(
                p ? bmid : bm, p ? b1 : b0, p ? bp : bmid,
                p ? cp : cmid,
                p ? dp : dmid, p ? d1 : d0, p ? dmid : dm,
                p ? cmid : cm,
                fc1);

            res0[2 * p]     = lbp_res(u0 & 0x3FFu);
            res0[2 * p + 1] = lbp_res((u0 >> 16) & 0x3FFu);
            res1[2 * p]     = lbp_res(u1 & 0x3FFu);
            res1[2 * p + 1] = lbp_res((u1 >> 16) & 0x3FFu);
        }
        *reinterpret_cast<float4*>(op0 + 128 * k) = make_float4(res0[0], res0[1], res0[2], res0[3]);
        *reinterpret_cast<float4*>(op1 + 128 * k) = make_float4(res1[0], res1[1], res1[2], res1[3]);

        // rotate pipeline state
        pa1 = a1; pb1 = b1; pc1 = c1; pd1 = d1;
        a0 = na0; a1 = na1; b0 = nb0; b1 = nb1;
        c0 = nc0; c1 = nc1; d0 = nd0; d1 = nd1;
    }
}

extern "C" void kernel_launch(void* const* d_in, const int* in_sizes, int n_in,
                              void* d_out, int out_size) {
    const float* x = (const float*)d_in[0];
    float* out = (float*)d_out;
    const int nrows  = out_size / IMG_W;   // B*C*H = 49152
    const int npairs = nrows / 2;          // 24576 warps, 1 row-pair/warp
    const int threads = 256;               // 8 warps/block
    const int blocks = (npairs + 7) / 8;
    lbp_kernel<<<blocks, threads>>>(x, out, npairs);
}

// round 16
// speedup vs baseline: 1.0190x; 1.0190x over previous
#include <cuda_runtime.h>
#include <cuda_fp16.h>

// LBP uniform (P=8, R=1) over (B,C,H,W)=(32,3,512,512) float32.
// R16 = R12 exactly (proven lowest issued-work: 2 out rows/warp, pipelined
// coalesced chunks, f16x2 compares, f32x2 packed scaling, STG.128, weights
// in REGISTERS, launch_bounds(256,5)) + two latency-only deltas:
//  - depth-3 hfma2 tree (same op count as depth-7 chain, ~1/3 the exposed lat)
//  - float(lbp)/255 via int_as_float(0x4B000000|lbp) + exact FFMA
//    (kills 20-cyc XU I2F + FMUL; same op count, 4-cyc fma pipe)

#define IMG_W 512
#define IMG_H 512
#define FULL 0xFFFFFFFFu

__device__ __forceinline__ unsigned prmt(unsigned a, unsigned b, unsigned sel) {
    unsigned d;
    asm("prmt.b32 %0, %1, %2, %3;" : "=r"(d) : "r"(a), "r"(b), "r"(sel));
    return d;
}

// two packed floats (lo,hi) * 255 -> f16x2 (RZ). Exact: RN f32 mul then RZ.
__device__ __forceinline__ unsigned conv2(unsigned long long px2) {
    unsigned d;
    asm("{\n\t"
        ".reg .b64 t;\n\t"
        ".reg .f32 lo, hi;\n\t"
        "mul.rn.f32x2 t, %1, %2;\n\t"
        "mov.b64 {lo, hi}, t;\n\t"
        "cvt.rz.f16x2.f32 %0, hi, lo;\n\t"
        "}"
        : "=r"(d) : "l"(px2), "l"(0x437F0000437F0000ull));  // 255.0f x2
    return d;
}

__device__ __forceinline__ __half2 u2h(unsigned x) {
    __half2 h;
    *reinterpret_cast<unsigned*>(&h) = x;
    return h;
}

// uniform-LBP tail from 8-bit code (no I2F/FMUL: bias trick + exact FFMA)
__device__ __forceinline__ float lbp_res(unsigned m) {
    const unsigned mm  = m * 0x101u;          // m | m<<8
    const unsigned rot = (mm >> 7) & 0xFFu;   // circular rot-left-1
    const int trans = __popc(m ^ rot);
    const int ones  = __popc(m);
    const int lbp   = (trans <= 2) ? ones : 9;
    const float f = __int_as_float(0x4B000000 | lbp);   // exactly 2^23 + lbp
    // fma(f, 1/255, -2^23/255 rounded): cancellation exact -> RN(lbp/255)
    return fmaf(f, 1.0f / 255.0f, -32896.50390625f);
}

// load one chunk (4 px) of one row, convert to two f16x2 words
__device__ __forceinline__ void load4(const float* p, unsigned& w0, unsigned& w1) {
    const ulonglong2 u = *reinterpret_cast<const ulonglong2*>(p);
    w0 = conv2(u.x);
    w1 = conv2(u.y);
}

__global__ __launch_bounds__(256, 5)
void lbp_kernel(const float* __restrict__ x, float* __restrict__ out, int npairs) {
    const int pr   = blockIdx.x * (blockDim.x >> 5) + (threadIdx.x >> 5);
    const int lane = threadIdx.x & 31;
    if (pr >= npairs) return;

    const int r0 = pr * 2;                 // even; pair stays inside one image
    const int h0 = r0 & (IMG_H - 1);
    const bool hasTop = (h0 != 0);
    const bool hasBot = (h0 != IMG_H - 2);

    const float* rb = x + (size_t)r0 * IMG_W + lane * 4;   // row r0
    const float* ra = rb - IMG_W;                           // row r0-1
    const float* rc = rb + IMG_W;                           // row r0+1
    const float* rd = rb + 2 * IMG_W;                       // row r0+2
    float* op0 = out + (size_t)r0 * IMG_W + lane * 4;
    float* op1 = op0 + IMG_W;

    const int upLane = (lane + 31) & 31;
    const int dnLane = (lane + 1) & 31;

    // register-resident tree weights (NOT immediates — ptxas can't encode
    // half2 consts inline; R14/R15 showed inline forms add MOV traffic)
    const __half2 TWO  = u2h(0x40004000u);
    const __half2 FOUR = u2h(0x44004400u);
    const __half2 SIXT = u2h(0x4C004C00u);

    // prev-chunk edge words (word[1]) per row; 0 at left image border
    unsigned pa1 = 0u, pb1 = 0u, pc1 = 0u, pd1 = 0u;
    // current chunk: rows a (top), b (=r0), c (=r1), d (bottom)
    unsigned a0, a1, b0, b1, c0, c1, d0, d1;
    if (hasTop) load4(ra, a0, a1); else { a0 = 0u; a1 = 0u; }
    load4(rb, b0, b1);
    load4(rc, c0, c1);
    if (hasBot) load4(rd, d0, d1); else { d0 = 0u; d1 = 0u; }

#pragma unroll
    for (int k = 0; k < 4; k++) {
        // lookahead: next chunk
        unsigned na0 = 0u, na1 = 0u, nb0 = 0u, nb1 = 0u;
        unsigned nc0 = 0u, nc1 = 0u, nd0 = 0u, nd1 = 0u;
        if (k < 3) {
            const int off = 128 * (k + 1);
            if (hasTop) load4(ra + off, na0, na1);
            load4(rb + off, nb0, nb1);
            load4(rc + off, nc0, nc1);
            if (hasBot) load4(rd + off, nd0, nd1);
        }

        // halos: left = word1 of lane-1 (lane0 <- lane31's prev chunk);
        //        right = word0 of lane+1 (lane31 <- lane0's next chunk)
        unsigned ls, rs;
        ls = (lane == 31) ? pa1 : a1;  const unsigned aal = __shfl_sync(FULL, ls, upLane);
        rs = (lane == 0)  ? na0 : a0;  const unsigned aar = __shfl_sync(FULL, rs, dnLane);
        ls = (lane == 31) ? pb1 : b1;  const unsigned bal = __shfl_sync(FULL, ls, upLane);
        rs = (lane == 0)  ? nb0 : b0;  const unsigned bar = __shfl_sync(FULL, rs, dnLane);
        ls = (lane == 31) ? pc1 : c1;  const unsigned cal = __shfl_sync(FULL, ls, upLane);
        rs = (lane == 0)  ? nc0 : c0;  const unsigned car = __shfl_sync(FULL, rs, dnLane);
        ls = (lane == 31) ? pd1 : d1;  const unsigned dal = __shfl_sync(FULL, ls, upLane);
        rs = (lane == 0)  ? nd0 : d0;  const unsigned dar = __shfl_sync(FULL, rs, dnLane);

        // shifted windows per row: m=(px-1,px0) mid=(px1,px2) p=(px3,px4)
        const unsigned am = prmt(aal, a0, 0x5432u), amid = prmt(a0, a1, 0x5432u), ap = prmt(a1, aar, 0x5432u);
        const unsigned bm = prmt(bal, b0, 0x5432u), bmid = prmt(b0, b1, 0x5432u), bp = prmt(b1, bar, 0x5432u);
        const unsigned cm = prmt(cal, c0, 0x5432u), cmid = prmt(c0, c1, 0x5432u), cp = prmt(c1, car, 0x5432u);
        const unsigned dm = prmt(dal, d0, 0x5432u), dmid = prmt(d0, d1, 0x5432u), dp = prmt(d1, dar, 0x5432u);

        float res0[4], res1[4];
#pragma unroll
        for (int p = 0; p < 2; p++) {
            // output row 0: top=a, center=b, bottom=c
            const __half2 fc0 = h2floor(u2h(p ? b1 : b0));
            // output row 1: top=b, center=c, bottom=d
            const __half2 fc1 = h2floor(u2h(p ? c1 : c0));

            const unsigned tl0 = p ? amid : am, tc0 = p ? a1 : a0, tr0 = p ? ap : amid;
            const unsigned cl0 = p ? bmid : bm, cr0 = p ? bp : bmid;
            const unsigned bl0 = p ? cmid : cm, bc0 = p ? c1 : c0, br0 = p ? cp : cmid;

            const unsigned tl1 = p ? bmid : bm, tc1 = p ? b1 : b0, tr1 = p ? bp : bmid;
            const unsigned cl1 = p ? cmid : cm, cr1 = p ? cp : cmid;
            const unsigned bl1 = p ? dmid : dm, bc1 = p ? d1 : d0, br1 = p ? dp : dmid;

            // two independent depth-3 trees (circular order: tl,t,tr,r,br,b,bl,l
            //  -> weights 1,2,4,8,16,32,64,128)
            const __half2 g0a = __hge2(u2h(tl0), fc0), g0b = __hge2(u2h(tl1), fc1);
            const __half2 g1a = __hge2(u2h(tc0), fc0), g1b = __hge2(u2h(tc1), fc1);
            const __half2 g2a = __hge2(u2h(tr0), fc0), g2b = __hge2(u2h(tr1), fc1);
            const __half2 g3a = __hge2(u2h(cr0), fc0), g3b = __hge2(u2h(cr1), fc1);
            const __half2 g4a = __hge2(u2h(br0), fc0), g4b = __hge2(u2h(br1), fc1);
            const __half2 g5a = __hge2(u2h(bc0), fc0), g5b = __hge2(u2h(bc1), fc1);
            const __half2 g6a = __hge2(u2h(bl0), fc0), g6b = __hge2(u2h(bl1), fc1);
            const __half2 g7a = __hge2(u2h(cl0), fc0), g7b = __hge2(u2h(cl1), fc1);

            const __half2 u01a = __hfma2(g1a, TWO, g0a);   // 1,2
            const __half2 u23a = __hfma2(g3a, TWO, g2a);   // (4,8)/4
            const __half2 u45a = __hfma2(g5a, TWO, g4a);   // (16,32)/16
            const __half2 u67a = __hfma2(g7a, TWO, g6a);   // (64,128)/64
            const __half2 v0a  = __hfma2(u23a, FOUR, u01a);
            const __half2 v1a  = __hfma2(u67a, FOUR, u45a);
            const __half2 m0   = __hfma2(v1a, SIXT, v0a);

            const __half2 u01b = __hfma2(g1b, TWO, g0b);
            const __half2 u23b = __hfma2(g3b, TWO, g2b);
            const __half2 u45b = __hfma2(g5b, TWO, g4b);
            const __half2 u67b = __hfma2(g7b, TWO, g6b);
            const __half2 v0b  = __hfma2(u23b, FOUR, u01b);
            const __half2 v1b  = __hfma2(u67b, FOUR, u45b);
            const __half2 m1   = __hfma2(v1b, SIXT, v0b);

            res0[2 * p]     = lbp_res((unsigned)__half2int_rz(__low2half(m0)));
            res0[2 * p + 1] = lbp_res((unsigned)__half2int_rz(__high2half(m0)));
            res1[2 * p]     = lbp_res((unsigned)__half2int_rz(__low2half(m1)));
            res1[2 * p + 1] = lbp_res((unsigned)__half2int_rz(__high2half(m1)));
        }
        *reinterpret_cast<float4*>(op0 + 128 * k) = make_float4(res0[0], res0[1], res0[2], res0[3]);
        *reinterpret_cast<float4*>(op1 + 128 * k) = make_float4(res1[0], res1[1], res1[2], res1[3]);

        // rotate pipeline state
        pa1 = a1; pb1 = b1; pc1 = c1; pd1 = d1;
        a0 = na0; a1 = na1; b0 = nb0; b1 = nb1;
        c0 = nc0; c1 = nc1; d0 = nd0; d1 = nd1;
    }
}

extern "C" void kernel_launch(void* const* d_in, const int* in_sizes, int n_in,
                              void* d_out, int out_size) {
    const float* x = (const float*)d_in[0];
    float* out = (float*)d_out;
    const int nrows  = out_size / IMG_W;   // B*C*H = 49152
    const int npairs = nrows / 2;          // 24576 warps, 1 row-pair/warp
    const int threads = 256;               // 8 warps/block
    const int blocks = (npairs + 7) / 8;
    lbp_kernel<<<blocks, threads>>>(x, out, npairs);
}

// round 17
// speedup vs baseline: 1.0557x; 1.0360x over previous
#include <cuda_runtime.h>
#include <cuda_fp16.h>

// LBP uniform (P=8, R=1) over (B,C,H,W)=(32,3,512,512) float32.
// R17 = R12 byte-identical structure (proven lowest issued-work: 2 out
// rows/warp, pipelined coalesced chunks, f16x2 compares with SERIAL weighted
// chain and register-resident weights, f32x2 packed scaling, STG.128,
// launch_bounds(256,5)) + strictly-free deltas only:
//  - tail: float(lbp)/255 via int_as_float(0x4B000000|lbp) + one exact FFMA
//    (drops 20-cyc XU I2F + FMUL; equal op count on 4-cyc pipes)
//  - stores: st.global.cs (output never re-read; keep input rows in L2)

#define IMG_W 512
#define IMG_H 512
#define FULL 0xFFFFFFFFu

__device__ __forceinline__ unsigned prmt(unsigned a, unsigned b, unsigned sel) {
    unsigned d;
    asm("prmt.b32 %0, %1, %2, %3;" : "=r"(d) : "r"(a), "r"(b), "r"(sel));
    return d;
}

// two packed floats (lo,hi) * 255 -> f16x2 (RZ). Exact: RN f32 mul then RZ.
__device__ __forceinline__ unsigned conv2(unsigned long long px2) {
    unsigned d;
    asm("{\n\t"
        ".reg .b64 t;\n\t"
        ".reg .f32 lo, hi;\n\t"
        "mul.rn.f32x2 t, %1, %2;\n\t"
        "mov.b64 {lo, hi}, t;\n\t"
        "cvt.rz.f16x2.f32 %0, hi, lo;\n\t"
        "}"
        : "=r"(d) : "l"(px2), "l"(0x437F0000437F0000ull));  // 255.0f x2
    return d;
}

__device__ __forceinline__ __half2 u2h(unsigned x) {
    __half2 h;
    *reinterpret_cast<unsigned*>(&h) = x;
    return h;
}

// weighted accumulate: m += (a >= c) * W   (W register-resident half2)
#define ACC(mreg, aval, cval, W) \
    mreg = __hfma2(__hge2(u2h(aval), cval), W, mreg)

// uniform-LBP tail: no I2F/FMUL (bias trick + exact FFMA)
__device__ __forceinline__ float lbp_res(unsigned m) {
    const unsigned mm  = m * 0x101u;          // m | m<<8
    const unsigned rot = (mm >> 7) & 0xFFu;   // circular rot-left-1
    const int trans = __popc(m ^ rot);
    const int ones  = __popc(m);
    const int lbp   = (trans <= 2) ? ones : 9;
    const float f = __int_as_float(0x4B000000 | lbp);   // exactly 2^23 + lbp
    return fmaf(f, 1.0f / 255.0f, -32896.50390625f);    // = RN(lbp/255)
}

// load one chunk (4 px) of one row, convert to two f16x2 words
__device__ __forceinline__ void load4(const float* p, unsigned& w0, unsigned& w1) {
    const ulonglong2 u = *reinterpret_cast<const ulonglong2*>(p);
    w0 = conv2(u.x);
    w1 = conv2(u.y);
}

__device__ __forceinline__ void store4_cs(float* p, float x, float y, float z, float w) {
    asm volatile("st.global.cs.v4.f32 [%0], {%1, %2, %3, %4};"
                 :: "l"(p), "f"(x), "f"(y), "f"(z), "f"(w) : "memory");
}

__global__ __launch_bounds__(256, 5)
void lbp_kernel(const float* __restrict__ x, float* __restrict__ out, int npairs) {
    const int pr   = blockIdx.x * (blockDim.x >> 5) + (threadIdx.x >> 5);
    const int lane = threadIdx.x & 31;
    if (pr >= npairs) return;

    const int r0 = pr * 2;                 // even; pair stays inside one image
    const int h0 = r0 & (IMG_H - 1);
    const bool hasTop = (h0 != 0);
    const bool hasBot = (h0 != IMG_H - 2);

    const float* rb = x + (size_t)r0 * IMG_W + lane * 4;   // row r0
    const float* ra = rb - IMG_W;                           // row r0-1
    const float* rc = rb + IMG_W;                           // row r0+1
    const float* rd = rb + 2 * IMG_W;                       // row r0+2
    float* op0 = out + (size_t)r0 * IMG_W + lane * 4;
    float* op1 = op0 + IMG_W;

    const int upLane = (lane + 31) & 31;
    const int dnLane = (lane + 1) & 31;

    // register-resident weights (R12 codegen — immediates add MOV traffic)
    const __half2 W2   = u2h(0x40004000u);
    const __half2 W4   = u2h(0x44004400u);
    const __half2 W8   = u2h(0x48004800u);
    const __half2 W16  = u2h(0x4C004C00u);
    const __half2 W32  = u2h(0x50005000u);
    const __half2 W64  = u2h(0x54005400u);
    const __half2 W128 = u2h(0x58005800u);

    // prev-chunk edge words (word[1]) per row; 0 at left image border
    unsigned pa1 = 0u, pb1 = 0u, pc1 = 0u, pd1 = 0u;
    // current chunk: rows a (top), b (=r0), c (=r1), d (bottom)
    unsigned a0, a1, b0, b1, c0, c1, d0, d1;
    if (hasTop) load4(ra, a0, a1); else { a0 = 0u; a1 = 0u; }
    load4(rb, b0, b1);
    load4(rc, c0, c1);
    if (hasBot) load4(rd, d0, d1); else { d0 = 0u; d1 = 0u; }

#pragma unroll
    for (int k = 0; k < 4; k++) {
        // lookahead: next chunk
        unsigned na0 = 0u, na1 = 0u, nb0 = 0u, nb1 = 0u;
        unsigned nc0 = 0u, nc1 = 0u, nd0 = 0u, nd1 = 0u;
        if (k < 3) {
            const int off = 128 * (k + 1);
            if (hasTop) load4(ra + off, na0, na1);
            load4(rb + off, nb0, nb1);
            load4(rc + off, nc0, nc1);
            if (hasBot) load4(rd + off, nd0, nd1);
        }

        // halos: left = word1 of lane-1 (lane0 <- lane31's prev chunk);
        //        right = word0 of lane+1 (lane31 <- lane0's next chunk)
        unsigned ls, rs;
        ls = (lane == 31) ? pa1 : a1;  const unsigned aal = __shfl_sync(FULL, ls, upLane);
        rs = (lane == 0)  ? na0 : a0;  const unsigned aar = __shfl_sync(FULL, rs, dnLane);
        ls = (lane == 31) ? pb1 : b1;  const unsigned bal = __shfl_sync(FULL, ls, upLane);
        rs = (lane == 0)  ? nb0 : b0;  const unsigned bar = __shfl_sync(FULL, rs, dnLane);
        ls = (lane == 31) ? pc1 : c1;  const unsigned cal = __shfl_sync(FULL, ls, upLane);
        rs = (lane == 0)  ? nc0 : c0;  const unsigned car = __shfl_sync(FULL, rs, dnLane);
        ls = (lane == 31) ? pd1 : d1;  const unsigned dal = __shfl_sync(FULL, ls, upLane);
        rs = (lane == 0)  ? nd0 : d0;  const unsigned dar = __shfl_sync(FULL, rs, dnLane);

        // shifted windows per row: m=(px-1,px0) mid=(px1,px2) p=(px3,px4)
        const unsigned am = prmt(aal, a0, 0x5432u), amid = prmt(a0, a1, 0x5432u), ap = prmt(a1, aar, 0x5432u);
        const unsigned bm = prmt(bal, b0, 0x5432u), bmid = prmt(b0, b1, 0x5432u), bp = prmt(b1, bar, 0x5432u);
        const unsigned cm = prmt(cal, c0, 0x5432u), cmid = prmt(c0, c1, 0x5432u), cp = prmt(c1, car, 0x5432u);
        const unsigned dm = prmt(dal, d0, 0x5432u), dmid = prmt(d0, d1, 0x5432u), dp = prmt(d1, dar, 0x5432u);

        float res0[4], res1[4];
#pragma unroll
        for (int p = 0; p < 2; p++) {
            // output row 0: top=a, center=b, bottom=c
            const __half2 fc0 = h2floor(u2h(p ? b1 : b0));
            // output row 1: top=b, center=c, bottom=d
            const __half2 fc1 = h2floor(u2h(p ? c1 : c0));

            const unsigned tl0 = p ? amid : am, tc0 = p ? a1 : a0, tr0 = p ? ap : amid;
            const unsigned cl0 = p ? bmid : bm, cr0 = p ? bp : bmid;
            const unsigned bl0 = p ? cmid : cm, bc0 = p ? c1 : c0, br0 = p ? cp : cmid;

            const unsigned tl1 = p ? bmid : bm, tc1 = p ? b1 : b0, tr1 = p ? bp : bmid;
            const unsigned cl1 = p ? cmid : cm, cr1 = p ? cp : cmid;
            const unsigned bl1 = p ? dmid : dm, bc1 = p ? d1 : d0, br1 = p ? dp : dmid;

            // two independent serial chains (circular: tl,t,tr,r,br,b,bl,l)
            __half2 m0 = __hge2(u2h(tl0), fc0);
            __half2 m1 = __hge2(u2h(tl1), fc1);
            ACC(m0, tc0, fc0, W2);    ACC(m1, tc1, fc1, W2);
            ACC(m0, tr0, fc0, W4);    ACC(m1, tr1, fc1, W4);
            ACC(m0, cr0, fc0, W8);    ACC(m1, cr1, fc1, W8);
            ACC(m0, br0, fc0, W16);   ACC(m1, br1, fc1, W16);
            ACC(m0, bc0, fc0, W32);   ACC(m1, bc1, fc1, W32);
            ACC(m0, bl0, fc0, W64);   ACC(m1, bl1, fc1, W64);
            ACC(m0, cl0, fc0, W128);  ACC(m1, cl1, fc1, W128);

            res0[2 * p]     = lbp_res((unsigned)__half2int_rz(__low2half(m0)));
            res0[2 * p + 1] = lbp_res((unsigned)__half2int_rz(__high2half(m0)));
            res1[2 * p]     = lbp_res((unsigned)__half2int_rz(__low2half(m1)));
            res1[2 * p + 1] = lbp_res((unsigned)__half2int_rz(__high2half(m1)));
        }
        store4_cs(op0 + 128 * k, res0[0], res0[1], res0[2], res0[3]);
        store4_cs(op1 + 128 * k, res1[0], res1[1], res1[2], res1[3]);

        // rotate pipeline state
        pa1 = a1; pb1 = b1; pc1 = c1; pd1 = d1;
        a0 = na0; a1 = na1; b0 = nb0; b1 = nb1;
        c0 = nc0; c1 = nc1; d0 = nd0; d1 = nd1;
    }
}

extern "C" void kernel_launch(void* const* d_in, const int* in_sizes, int n_in,
                              void* d_out, int out_size) {
    const float* x = (const float*)d_in[0];
    float* out = (float*)d_out;
    const int nrows  = out_size / IMG_W;   // B*C*H = 49152
    const int npairs = nrows / 2;          // 24576 warps, 1 row-pair/warp
    const int threads = 256;               // 8 warps/block
    const int blocks = (npairs + 7) / 8;
    lbp_kernel<<<blocks, threads>>>(x, out, npairs);
}